// round 1
// baseline (speedup 1.0000x reference)
#include <cuda_runtime.h>
#include <math.h>
#include <float.h>

#define NP    2048
#define MAXNP 256
#define TPV   128     // points per tile
#define H2STR 132     // padded stride for H2 [k][p]
#define W2STR 68      // padded stride for W2^T [j][k]

// shared memory layout (float offsets)
#define OFF_W1    0                 // 3*64 = 192
#define OFF_B1    192               // 64
#define OFF_W2T   256               // 128*68 = 8704
#define OFF_B2    8960              // 128
#define OFF_B3    9088              // 256
#define OFF_WH    9344              // 7*256 = 1792 (cls + 6 reg columns)
#define OFF_BH    11136             // 8 (bc, br[0..5], pad)
#define OFF_PTS   11144             // 128*3 = 384
#define OFF_H1    11528             // 131*64 = 8384 (3 pad rows for OOB-safe reads)
#define OFF_H2    19912             // 128*132 = 16896
#define OFF_FEATS 36808             // 256
#define SMEM_FLOATS 37064

extern __shared__ float s[];

__global__ __launch_bounds__(256, 1)
void refine_kernel(const float* __restrict__ points,
                   const int*   __restrict__ counts,
                   const float* __restrict__ proposals,
                   const float* __restrict__ W1, const float* __restrict__ b1,
                   const float* __restrict__ W2, const float* __restrict__ b2,
                   const float* __restrict__ W3, const float* __restrict__ b3,
                   const float* __restrict__ Wc, const float* __restrict__ bc,
                   const float* __restrict__ Wr, const float* __restrict__ br,
                   float* __restrict__ out)
{
    const int t = threadIdx.x;

    // ---- stage weights into smem (once per CTA) ----
    for (int i = t; i < 192; i += 256) s[OFF_W1 + i] = W1[i];
    if (t < 64)  s[OFF_B1 + t] = b1[t];
    for (int i = t; i < 8192; i += 256) {        // W2 (64x128) -> W2^T padded
        int k = i >> 7, j = i & 127;
        s[OFF_W2T + j * W2STR + k] = W2[i];
    }
    if (t < 128) s[OFF_B2 + t] = b2[t];
    s[OFF_B3 + t] = b3[t];
    s[OFF_WH + t] = Wc[t];                       // head col 0 = Wc
    #pragma unroll
    for (int j = 0; j < 6; j++) s[OFF_WH + (1 + j) * 256 + t] = Wr[t * 6 + j];
    if (t == 0) s[OFF_BH] = bc[0];
    if (t >= 1 && t < 7) s[OFF_BH + t] = br[t - 1];

    // W3 column for my channel lives in registers (full unroll keeps it there)
    float w3[128];
    #pragma unroll
    for (int k = 0; k < 128; k++) w3[k] = W3[k * 256 + t];

    __syncthreads();

    const int jch = t & 127;       // layer-2 channel
    const int pp  = t >> 7;        // layer-2 point-group half
    const int c1  = t & 63;        // layer-1 channel
    const int pb1 = t >> 6;        // layer-1 point offset

    const float w10 = s[OFF_W1 + c1];
    const float w11 = s[OFF_W1 + 64 + c1];
    const float w12 = s[OFF_W1 + 128 + c1];
    const float bb1 = s[OFF_B1 + c1];
    const float bb2 = s[OFF_B2 + jch];
    const float bb3 = s[OFF_B3 + t];

    for (int pid = blockIdx.x; pid < NP; pid += gridDim.x) {
        const int n = counts[pid];
        if (n < 4) {   // invalid: feats = 0 -> outputs are biases
            if (t == 0) out[pid] = s[OFF_BH];
            if (t < 6)  out[NP + pid * 6 + t] = s[OFF_BH + 1 + t];
            continue;
        }

        const float cen0 = proposals[pid * 6 + 0];
        const float cen1 = proposals[pid * 6 + 1];
        const float cen2 = proposals[pid * 6 + 2];
        const float is0 = 1.0f / (fabsf(proposals[pid * 6 + 3]) + 1e-6f);
        const float is1 = 1.0f / (fabsf(proposals[pid * 6 + 4]) + 1e-6f);
        const float is2 = 1.0f / (fabsf(proposals[pid * 6 + 5]) + 1e-6f);

        float m = -FLT_MAX;

        for (int p0b = 0; p0b < n; p0b += TPV) {
            const int tp = min(TPV, n - p0b);
            __syncthreads();   // smem reuse barrier (also orders prev head-reduce)

            // ---- canon points into smem ----
            const float* gp = points + (size_t)pid * (MAXNP * 3) + p0b * 3;
            for (int jj = t; jj < tp * 3; jj += 256) {
                const int d = jj % 3;
                const float v  = gp[jj];
                const float cc = (d == 0) ? cen0 : ((d == 1) ? cen1 : cen2);
                const float ii = (d == 0) ? is0  : ((d == 1) ? is1  : is2);
                s[OFF_PTS + jj] = (v - cc) * ii;
            }
            __syncthreads();

            // ---- layer 1: H1[p][c] ----
            for (int p = pb1; p < tp; p += 4) {
                const float x0 = s[OFF_PTS + p * 3 + 0];
                const float x1 = s[OFF_PTS + p * 3 + 1];
                const float x2 = s[OFF_PTS + p * 3 + 2];
                float a = fmaf(x0, w10, fmaf(x1, w11, fmaf(x2, w12, bb1)));
                s[OFF_H1 + p * 64 + c1] = fmaxf(a, 0.0f);
            }
            __syncthreads();

            // ---- layer 2: H2[k=j][p] ----
            for (int pb = pp * 4; pb < tp; pb += 8) {
                float a0 = bb2, a1 = bb2, a2 = bb2, a3 = bb2;
                #pragma unroll
                for (int k0 = 0; k0 < 64; k0 += 4) {
                    const float4 w4 = *(const float4*)&s[OFF_W2T + jch * W2STR + k0];
                    const float4 h0 = *(const float4*)&s[OFF_H1 + (pb + 0) * 64 + k0];
                    const float4 h1v = *(const float4*)&s[OFF_H1 + (pb + 1) * 64 + k0];
                    const float4 h2v = *(const float4*)&s[OFF_H1 + (pb + 2) * 64 + k0];
                    const float4 h3v = *(const float4*)&s[OFF_H1 + (pb + 3) * 64 + k0];
                    a0 = fmaf(h0.x,  w4.x, a0); a0 = fmaf(h0.y,  w4.y, a0);
                    a0 = fmaf(h0.z,  w4.z, a0); a0 = fmaf(h0.w,  w4.w, a0);
                    a1 = fmaf(h1v.x, w4.x, a1); a1 = fmaf(h1v.y, w4.y, a1);
                    a1 = fmaf(h1v.z, w4.z, a1); a1 = fmaf(h1v.w, w4.w, a1);
                    a2 = fmaf(h2v.x, w4.x, a2); a2 = fmaf(h2v.y, w4.y, a2);
                    a2 = fmaf(h2v.z, w4.z, a2); a2 = fmaf(h2v.w, w4.w, a2);
                    a3 = fmaf(h3v.x, w4.x, a3); a3 = fmaf(h3v.y, w4.y, a3);
                    a3 = fmaf(h3v.z, w4.z, a3); a3 = fmaf(h3v.w, w4.w, a3);
                }
                if (pb + 0 < tp) s[OFF_H2 + jch * H2STR + pb + 0] = fmaxf(a0, 0.0f);
                if (pb + 1 < tp) s[OFF_H2 + jch * H2STR + pb + 1] = fmaxf(a1, 0.0f);
                if (pb + 2 < tp) s[OFF_H2 + jch * H2STR + pb + 2] = fmaxf(a2, 0.0f);
                if (pb + 3 < tp) s[OFF_H2 + jch * H2STR + pb + 3] = fmaxf(a3, 0.0f);
            }
            __syncthreads();

            // ---- layer 3 + running max (channel t) ----
            for (int p0 = 0; p0 < tp; p0 += 8) {
                float a0 = 0.f, a1 = 0.f, a2 = 0.f, a3 = 0.f;
                float a4 = 0.f, a5 = 0.f, a6 = 0.f, a7 = 0.f;
                #pragma unroll
                for (int k = 0; k < 128; k++) {
                    const float4 ha = *(const float4*)&s[OFF_H2 + k * H2STR + p0];
                    const float4 hb = *(const float4*)&s[OFF_H2 + k * H2STR + p0 + 4];
                    const float w = w3[k];
                    a0 = fmaf(ha.x, w, a0); a1 = fmaf(ha.y, w, a1);
                    a2 = fmaf(ha.z, w, a2); a3 = fmaf(ha.w, w, a3);
                    a4 = fmaf(hb.x, w, a4); a5 = fmaf(hb.y, w, a5);
                    a6 = fmaf(hb.z, w, a6); a7 = fmaf(hb.w, w, a7);
                }
                const int lim = tp - p0;
                m = fmaxf(m, a0);
                if (lim > 1) m = fmaxf(m, a1);
                if (lim > 2) m = fmaxf(m, a2);
                if (lim > 3) m = fmaxf(m, a3);
                if (lim > 4) m = fmaxf(m, a4);
                if (lim > 5) m = fmaxf(m, a5);
                if (lim > 6) m = fmaxf(m, a6);
                if (lim > 7) m = fmaxf(m, a7);
            }
        }

        // ---- feats + heads ----
        s[OFF_FEATS + t] = m + bb3;
        __syncthreads();

        const int w = t >> 5, lane = t & 31;
        if (w < 7) {
            float acc = 0.0f;
            #pragma unroll
            for (int i = 0; i < 8; i++) {
                const int idx = i * 32 + lane;
                acc = fmaf(s[OFF_FEATS + idx], s[OFF_WH + w * 256 + idx], acc);
            }
            #pragma unroll
            for (int o = 16; o > 0; o >>= 1)
                acc += __shfl_xor_sync(0xffffffffu, acc, o);
            if (lane == 0) {
                if (w == 0) out[pid] = acc + s[OFF_BH];
                else        out[NP + pid * 6 + (w - 1)] = acc + s[OFF_BH + w];
            }
        }
    }
}

extern "C" void kernel_launch(void* const* d_in, const int* in_sizes, int n_in,
                              void* d_out, int out_size)
{
    const float* points    = (const float*)d_in[0];
    const int*   counts    = (const int*)  d_in[1];
    const float* proposals = (const float*)d_in[2];
    const float* W1 = (const float*)d_in[3];
    const float* b1 = (const float*)d_in[4];
    const float* W2 = (const float*)d_in[5];
    const float* b2 = (const float*)d_in[6];
    const float* W3 = (const float*)d_in[7];
    const float* b3 = (const float*)d_in[8];
    const float* Wc = (const float*)d_in[9];
    const float* bc = (const float*)d_in[10];
    const float* Wr = (const float*)d_in[11];
    const float* br = (const float*)d_in[12];
    float* out = (float*)d_out;

    int dev = 0, sms = 148;
    cudaGetDevice(&dev);
    cudaDeviceGetAttribute(&sms, cudaDevAttrMultiProcessorCount, dev);
    cudaFuncSetAttribute(refine_kernel,
                         cudaFuncAttributeMaxDynamicSharedMemorySize,
                         SMEM_FLOATS * (int)sizeof(float));

    refine_kernel<<<sms, 256, SMEM_FLOATS * (int)sizeof(float)>>>(
        points, counts, proposals, W1, b1, W2, b2, W3, b3, Wc, bc, Wr, br, out);
}

// round 5
// speedup vs baseline: 4.0714x; 4.0714x over previous
#include <cuda_runtime.h>
#include <math.h>
#include <float.h>

#define NP    2048
#define MAXNP 256

// ---- shared memory layout ----
// uint2 region first, then float region. Offsets in the respective units.
#define U2_H1P  0            // [128][36] u2  (H1 pairs: (k,k+4) tf32)
#define U2_H2P  4608         // [128][68] u2  (H2 pairs)
#define U2_W2P  13312        // [128][36] u2  (W2^T pairs)
#define H1STR   36
#define H2STR   68
#define W2STR   36
// float offsets
#define OFF_WH    35840      // 7*256 head weight columns (cls + 6 reg)
#define OFF_BH    37632      // 8
#define OFF_FEATS 37640      // 256
#define SMEM_FLOATS 37896    // 151,584 bytes

extern __shared__ float s[];

__device__ __forceinline__ unsigned f2tf(float f) {
    unsigned u; asm("cvt.rna.tf32.f32 %0, %1;" : "=r"(u) : "f"(f)); return u;
}

__device__ __forceinline__ void mma8(float& c0, float& c1, float& c2, float& c3,
                                     unsigned a0, unsigned a1, unsigned a2, unsigned a3,
                                     unsigned b0, unsigned b1) {
    asm("mma.sync.aligned.m16n8k8.row.col.f32.tf32.tf32.f32 "
        "{%0,%1,%2,%3}, {%4,%5,%6,%7}, {%8,%9}, {%0,%1,%2,%3};"
        : "+f"(c0), "+f"(c1), "+f"(c2), "+f"(c3)
        : "r"(a0), "r"(a1), "r"(a2), "r"(a3), "r"(b0), "r"(b1));
}

__global__ __launch_bounds__(512, 1)
void refine_kernel(const float* __restrict__ points,
                   const int*   __restrict__ counts,
                   const float* __restrict__ proposals,
                   const float* __restrict__ W1, const float* __restrict__ b1,
                   const float* __restrict__ W2, const float* __restrict__ b2,
                   const float* __restrict__ W3, const float* __restrict__ b3,
                   const float* __restrict__ Wc, const float* __restrict__ bc,
                   const float* __restrict__ Wr, const float* __restrict__ br,
                   float* __restrict__ out)
{
    uint2*    u2s = (uint2*)s;
    unsigned* us  = (unsigned*)s;

    const int tid  = threadIdx.x;
    const int w    = tid >> 5;           // warp 0..15
    const int lane = tid & 31;
    const int g    = lane >> 2;          // groupID 0..7
    const int tq   = lane & 3;           // tid-in-group 0..3

    // ---- stage W2^T pairs into smem (tf32) ----
    for (int i = tid; i < 128 * 32; i += 512) {
        const int ch = i >> 5, j = i & 31;
        const int ks = j >> 2, tt = j & 3;
        const int k = 8 * ks + tt;
        uint2 v;
        v.x = f2tf(W2[k * 128 + ch]);
        v.y = f2tf(W2[(k + 4) * 128 + ch]);
        u2s[U2_W2P + ch * W2STR + j] = v;
    }
    // ---- head weights/biases ----
    if (tid < 256) {
        s[OFF_WH + tid] = Wc[tid];
        #pragma unroll
        for (int j = 0; j < 6; j++) s[OFF_WH + (1 + j) * 256 + tid] = Wr[tid * 6 + j];
    }
    if (tid == 0) s[OFF_BH] = bc[0];
    if (tid >= 1 && tid < 7) s[OFF_BH + tid] = br[tid - 1];

    // ---- W3 A-fragments: resident in registers for the whole kernel ----
    // warp w owns output channels [16w, 16w+16)
    const int chw = 16 * w;
    unsigned a3r[64];
    #pragma unroll
    for (int ks = 0; ks < 16; ks++) {
        const int k0 = 8 * ks;
        a3r[4 * ks + 0] = f2tf(W3[(k0 + tq)     * 256 + chw + g]);
        a3r[4 * ks + 1] = f2tf(W3[(k0 + tq)     * 256 + chw + g + 8]);
        a3r[4 * ks + 2] = f2tf(W3[(k0 + tq + 4) * 256 + chw + g]);
        a3r[4 * ks + 3] = f2tf(W3[(k0 + tq + 4) * 256 + chw + g + 8]);
    }

    // layer-2 role: warp w handles channels [16*(w&7), +16), point half (w>>3)
    const int wm  = w & 7;
    const int chL2 = 16 * wm + g;
    const float bb2a = b2[chL2];
    const float bb2b = b2[chL2 + 8];
    const float bb3a = b3[chw + g];
    const float bb3b = b3[chw + g + 8];
    const int jsA = (8 * wm + (g & 3)) * 2 + ((g >> 2) & 1);  // uint slot of ch in H2 pair row
    const int l2half = w >> 3;

    __syncthreads();

    for (int pid = blockIdx.x; pid < NP; pid += gridDim.x) {
        const int n = counts[pid];
        if (n < 4) {
            if (tid == 0) out[pid] = s[OFF_BH];
            if (tid < 6)  out[NP + pid * 6 + tid] = s[OFF_BH + 1 + tid];
            continue;
        }

        // proposals row: pid*6 floats = 24*pid bytes -> always 8B aligned.
        const float2 pr0 = __ldg((const float2*)(proposals + pid * 6));      // cen0, cen1
        const float2 pr1 = __ldg((const float2*)(proposals + pid * 6 + 2));  // cen2, size0
        const float2 pr2 = __ldg((const float2*)(proposals + pid * 6 + 4));  // size1, size2
        const float cen0 = pr0.x, cen1 = pr0.y, cen2 = pr1.x;
        const float is0 = 1.0f / (fabsf(pr1.y) + 1e-6f);
        const float is1 = 1.0f / (fabsf(pr2.x) + 1e-6f);
        const float is2 = 1.0f / (fabsf(pr2.y) + 1e-6f);

        float chmax0 = -FLT_MAX, chmax1 = -FLT_MAX;

        for (int p0b = 0; p0b < n; p0b += 128) {
            const int tp = min(128, n - p0b);

            // ---- layer 1 (scalar): H1p[p][j] = tf32 relu pair ----
            for (int i = tid; i < 128 * 32; i += 512) {
                const int p = i >> 5, j = i & 31;
                const int ks = j >> 2, tt = j & 3;
                const int c0 = 8 * ks + tt, c1 = c0 + 4;
                const float* pt = points + (size_t)pid * (MAXNP * 3) + (p0b + p) * 3;
                const float x0 = (pt[0] - cen0) * is0;
                const float x1 = (pt[1] - cen1) * is1;
                const float x2 = (pt[2] - cen2) * is2;
                float h0 = fmaf(x2, W1[128 + c0], fmaf(x1, W1[64 + c0], fmaf(x0, W1[c0], b1[c0])));
                float h1 = fmaf(x2, W1[128 + c1], fmaf(x1, W1[64 + c1], fmaf(x0, W1[c1], b1[c1])));
                uint2 v;
                v.x = f2tf(fmaxf(h0, 0.0f));
                v.y = f2tf(fmaxf(h1, 0.0f));
                u2s[U2_H1P + p * H1STR + j] = v;
            }
            __syncthreads();

            // ---- layer 2: C^T[ch][p] = W2^T x H1^T (M=128ch, N=64pts/warp-half, K=64)
            //      nt processed in 2 groups of 4 to bound live accumulators.
            #pragma unroll
            for (int ng = 0; ng < 2; ng++) {
                const int n0b = 64 * l2half + 32 * ng;
                float acc[4][4];
                #pragma unroll
                for (int nt = 0; nt < 4; nt++) {
                    acc[nt][0] = 0.f; acc[nt][1] = 0.f; acc[nt][2] = 0.f; acc[nt][3] = 0.f;
                }
                #pragma unroll
                for (int ks = 0; ks < 8; ks++) {
                    const uint2 aP0 = u2s[U2_W2P + (16 * wm + g)     * W2STR + 4 * ks + tq];
                    const uint2 aP1 = u2s[U2_W2P + (16 * wm + g + 8) * W2STR + 4 * ks + tq];
                    #pragma unroll
                    for (int nt = 0; nt < 4; nt++) {
                        const uint2 bP = u2s[U2_H1P + (n0b + 8 * nt + g) * H1STR + 4 * ks + tq];
                        mma8(acc[nt][0], acc[nt][1], acc[nt][2], acc[nt][3],
                             aP0.x, aP1.x, aP0.y, aP1.y, bP.x, bP.y);
                    }
                }
                // epilogue: +b2, relu, tf32, store transposed pairs into H2p
                #pragma unroll
                for (int nt = 0; nt < 4; nt++) {
                    const int p0 = n0b + 8 * nt + 2 * tq;
                    const int base0 = 2 * U2_H2P + p0 * (2 * H2STR);
                    const int base1 = base0 + 2 * H2STR;
                    us[base0 + jsA]     = f2tf(fmaxf(acc[nt][0] + bb2a, 0.0f));
                    us[base1 + jsA]     = f2tf(fmaxf(acc[nt][1] + bb2a, 0.0f));
                    us[base0 + jsA + 8] = f2tf(fmaxf(acc[nt][2] + bb2b, 0.0f));
                    us[base1 + jsA + 8] = f2tf(fmaxf(acc[nt][3] + bb2b, 0.0f));
                }
            }
            __syncthreads();

            // ---- layer 3: C^T[ch][p] = W3^T x H2^T (M=256ch, N=128pts, K=128) + max
            //      4 groups of 4 mma-tiles (N=32 each) to bound live accumulators.
            #pragma unroll
            for (int ng = 0; ng < 4; ng++) {
                const int n0 = 32 * ng;
                float acc[4][4];
                #pragma unroll
                for (int nt = 0; nt < 4; nt++) {
                    acc[nt][0] = 0.f; acc[nt][1] = 0.f; acc[nt][2] = 0.f; acc[nt][3] = 0.f;
                }
                #pragma unroll
                for (int ks = 0; ks < 16; ks++) {
                    #pragma unroll
                    for (int nt = 0; nt < 4; nt++) {
                        const uint2 bP = u2s[U2_H2P + (n0 + 8 * nt + g) * H2STR + 4 * ks + tq];
                        mma8(acc[nt][0], acc[nt][1], acc[nt][2], acc[nt][3],
                             a3r[4 * ks + 0], a3r[4 * ks + 1], a3r[4 * ks + 2], a3r[4 * ks + 3],
                             bP.x, bP.y);
                    }
                }
                // masked max-pool over point columns
                #pragma unroll
                for (int nt = 0; nt < 4; nt++) {
                    const int p0 = n0 + 8 * nt + 2 * tq;
                    if (p0 < tp) {
                        chmax0 = fmaxf(chmax0, acc[nt][0]);
                        chmax1 = fmaxf(chmax1, acc[nt][2]);
                    }
                    if (p0 + 1 < tp) {
                        chmax0 = fmaxf(chmax0, acc[nt][1]);
                        chmax1 = fmaxf(chmax1, acc[nt][3]);
                    }
                }
            }
        }

        // ---- reduce max over the 4 tq lanes (covers all point columns) ----
        chmax0 = fmaxf(chmax0, __shfl_xor_sync(0xffffffffu, chmax0, 1));
        chmax0 = fmaxf(chmax0, __shfl_xor_sync(0xffffffffu, chmax0, 2));
        chmax1 = fmaxf(chmax1, __shfl_xor_sync(0xffffffffu, chmax1, 1));
        chmax1 = fmaxf(chmax1, __shfl_xor_sync(0xffffffffu, chmax1, 2));
        if (tq == 0) {
            s[OFF_FEATS + chw + g]     = chmax0 + bb3a;
            s[OFF_FEATS + chw + g + 8] = chmax1 + bb3b;
        }
        __syncthreads();

        // ---- heads: 7 dot products of length 256 (warps 0..6) ----
        if (w < 7) {
            float acc = 0.0f;
            #pragma unroll
            for (int i = 0; i < 8; i++) {
                const int idx = i * 32 + lane;
                acc = fmaf(s[OFF_FEATS + idx], s[OFF_WH + w * 256 + idx], acc);
            }
            #pragma unroll
            for (int o = 16; o > 0; o >>= 1)
                acc += __shfl_xor_sync(0xffffffffu, acc, o);
            if (lane == 0) {
                if (w == 0) out[pid] = acc + s[OFF_BH];
                else        out[NP + pid * 6 + (w - 1)] = acc + s[OFF_BH + w];
            }
        }
    }
}

extern "C" void kernel_launch(void* const* d_in, const int* in_sizes, int n_in,
                              void* d_out, int out_size)
{
    const float* points    = (const float*)d_in[0];
    const int*   counts    = (const int*)  d_in[1];
    const float* proposals = (const float*)d_in[2];
    const float* W1 = (const float*)d_in[3];
    const float* b1 = (const float*)d_in[4];
    const float* W2 = (const float*)d_in[5];
    const float* b2 = (const float*)d_in[6];
    const float* W3 = (const float*)d_in[7];
    const float* b3 = (const float*)d_in[8];
    const float* Wc = (const float*)d_in[9];
    const float* bc = (const float*)d_in[10];
    const float* Wr = (const float*)d_in[11];
    const float* br = (const float*)d_in[12];
    float* out = (float*)d_out;

    int dev = 0, sms = 148;
    cudaGetDevice(&dev);
    cudaDeviceGetAttribute(&sms, cudaDevAttrMultiProcessorCount, dev);
    cudaFuncSetAttribute(refine_kernel,
                         cudaFuncAttributeMaxDynamicSharedMemorySize,
                         SMEM_FLOATS * (int)sizeof(float));

    refine_kernel<<<sms, 512, SMEM_FLOATS * (int)sizeof(float)>>>(
        points, counts, proposals, W1, b1, W2, b2, W3, b3, Wc, bc, Wr, br, out);
}

// round 6
// speedup vs baseline: 4.6856x; 1.1508x over previous
#include <cuda_runtime.h>
#include <math.h>
#include <float.h>

#define NP    2048
#define MAXNP 256

// ---- shared memory layout ----
// uint4 quad arrays first (stride ≡ 4 mod 8 in 16B units -> conflict-free LDS.128),
// then float region. Offsets in the respective units.
#define Q4_H1   0            // [128 pts][20 u4]  (16 used: quad (16s+tq)+{0,4,8,12}, K=64)
#define Q4_H2   2560         // [128 pts][36 u4]  (32 used: K=128)
#define Q4_W2   7168         // [128 ch ][20 u4]  (W2^T quads, K=64)
#define H1Q 20
#define H2Q 36
#define W2Q 20
// float offsets (floats region starts after 9728 u4 = 38912 floats)
#define OFF_WH    38912      // 7*256 head weight columns (cls + 6 reg)
#define OFF_BH    40704      // 8
#define OFF_FEATS 40712      // 256
#define SMEM_FLOATS 40968    // 163,872 bytes

extern __shared__ float s[];

__device__ __forceinline__ unsigned f2tf(float f) {
    unsigned u; asm("cvt.rna.tf32.f32 %0, %1;" : "=r"(u) : "f"(f)); return u;
}

__device__ __forceinline__ void mma8(float& c0, float& c1, float& c2, float& c3,
                                     unsigned a0, unsigned a1, unsigned a2, unsigned a3,
                                     unsigned b0, unsigned b1) {
    asm("mma.sync.aligned.m16n8k8.row.col.f32.tf32.tf32.f32 "
        "{%0,%1,%2,%3}, {%4,%5,%6,%7}, {%8,%9}, {%0,%1,%2,%3};"
        : "+f"(c0), "+f"(c1), "+f"(c2), "+f"(c3)
        : "r"(a0), "r"(a1), "r"(a2), "r"(a3), "r"(b0), "r"(b1));
}

__global__ __launch_bounds__(512, 1)
void refine_kernel(const float* __restrict__ points,
                   const int*   __restrict__ counts,
                   const float* __restrict__ proposals,
                   const float* __restrict__ W1, const float* __restrict__ b1,
                   const float* __restrict__ W2, const float* __restrict__ b2,
                   const float* __restrict__ W3, const float* __restrict__ b3,
                   const float* __restrict__ Wc, const float* __restrict__ bc,
                   const float* __restrict__ Wr, const float* __restrict__ br,
                   float* __restrict__ out)
{
    uint4*    q4s = (uint4*)s;
    unsigned* us  = (unsigned*)s;

    const int tid  = threadIdx.x;
    const int w    = tid >> 5;           // warp 0..15
    const int lane = tid & 31;
    const int g    = lane >> 2;          // groupID 0..7
    const int tq   = lane & 3;           // tid-in-group 0..3

    // ---- stage W2^T quads into smem (tf32): quad(row, s, tq) = k in (16s+tq)+{0,4,8,12} ----
    for (int i = tid; i < 128 * 16; i += 512) {
        const int row = i >> 4, j = i & 15;
        const int sQ = j >> 2, tqQ = j & 3;
        const int k = 16 * sQ + tqQ;
        uint4 v;
        v.x = f2tf(W2[k * 128 + row]);
        v.y = f2tf(W2[(k + 4) * 128 + row]);
        v.z = f2tf(W2[(k + 8) * 128 + row]);
        v.w = f2tf(W2[(k + 12) * 128 + row]);
        q4s[Q4_W2 + row * W2Q + j] = v;
    }
    // ---- head weights/biases ----
    if (tid < 256) {
        s[OFF_WH + tid] = Wc[tid];
        #pragma unroll
        for (int j = 0; j < 6; j++) s[OFF_WH + (1 + j) * 256 + tid] = Wr[tid * 6 + j];
    }
    if (tid == 0) s[OFF_BH] = bc[0];
    if (tid >= 1 && tid < 7) s[OFF_BH + tid] = br[tid - 1];

    // ---- W3 A-fragments: resident in registers for the whole kernel ----
    // warp w owns output channels [16w, 16w+16)
    const int chw = 16 * w;
    unsigned a3r[64];
    #pragma unroll
    for (int ks = 0; ks < 16; ks++) {
        const int k0 = 8 * ks;
        a3r[4 * ks + 0] = f2tf(W3[(k0 + tq)     * 256 + chw + g]);
        a3r[4 * ks + 1] = f2tf(W3[(k0 + tq)     * 256 + chw + g + 8]);
        a3r[4 * ks + 2] = f2tf(W3[(k0 + tq + 4) * 256 + chw + g]);
        a3r[4 * ks + 3] = f2tf(W3[(k0 + tq + 4) * 256 + chw + g + 8]);
    }

    // layer-2 role: warp w handles channels [16*(w&7), +16), point half (w>>3)
    const int wm  = w & 7;
    const int chL2 = 16 * wm + g;
    const float bb2a = b2[chL2];
    const float bb2b = b2[chL2 + 8];
    const float bb3a = b3[chw + g];
    const float bb3b = b3[chw + g + 8];
    const int l2half = w >> 3;
    // H2 quad-layout scalar store index parts: uint idx = H2base + p*144 + wm*16 + (g&3)*4 + (g>>2)
    const int h2sbase = 4 * Q4_H2 + wm * 16 + (g & 3) * 4 + (g >> 2);

    __syncthreads();

    for (int pid = blockIdx.x; pid < NP; pid += gridDim.x) {
        const int n = counts[pid];
        if (n < 4) {
            if (tid == 0) out[pid] = s[OFF_BH];
            if (tid < 6)  out[NP + pid * 6 + tid] = s[OFF_BH + 1 + tid];
            continue;
        }

        // proposals row: pid*6 floats = 24*pid bytes -> always 8B aligned.
        const float2 pr0 = __ldg((const float2*)(proposals + pid * 6));      // cen0, cen1
        const float2 pr1 = __ldg((const float2*)(proposals + pid * 6 + 2));  // cen2, size0
        const float2 pr2 = __ldg((const float2*)(proposals + pid * 6 + 4));  // size1, size2
        const float cen0 = pr0.x, cen1 = pr0.y, cen2 = pr1.x;
        const float is0 = 1.0f / (fabsf(pr1.y) + 1e-6f);
        const float is1 = 1.0f / (fabsf(pr2.x) + 1e-6f);
        const float is2 = 1.0f / (fabsf(pr2.y) + 1e-6f);

        float chmax0 = -FLT_MAX, chmax1 = -FLT_MAX;

        for (int p0b = 0; p0b < n; p0b += 128) {
            const int tp = min(128, n - p0b);
            const int tp32 = (tp + 31) & ~31;   // round up to 32-point group

            // ---- layer 1 (scalar): H1 quads, only needed points ----
            for (int i = tid; i < tp32 * 16; i += 512) {
                const int p = i >> 4, j = i & 15;
                const int sQ = j >> 2, tqQ = j & 3;
                const int c = 16 * sQ + tqQ;
                const float* pt = points + (size_t)pid * (MAXNP * 3) + (p0b + p) * 3;
                const float x0 = (pt[0] - cen0) * is0;
                const float x1 = (pt[1] - cen1) * is1;
                const float x2 = (pt[2] - cen2) * is2;
                uint4 v;
                {
                    float h = fmaf(x2, W1[128 + c], fmaf(x1, W1[64 + c], fmaf(x0, W1[c], b1[c])));
                    v.x = f2tf(fmaxf(h, 0.0f));
                }
                {
                    float h = fmaf(x2, W1[128 + c + 4], fmaf(x1, W1[64 + c + 4], fmaf(x0, W1[c + 4], b1[c + 4])));
                    v.y = f2tf(fmaxf(h, 0.0f));
                }
                {
                    float h = fmaf(x2, W1[128 + c + 8], fmaf(x1, W1[64 + c + 8], fmaf(x0, W1[c + 8], b1[c + 8])));
                    v.z = f2tf(fmaxf(h, 0.0f));
                }
                {
                    float h = fmaf(x2, W1[128 + c + 12], fmaf(x1, W1[64 + c + 12], fmaf(x0, W1[c + 12], b1[c + 12])));
                    v.w = f2tf(fmaxf(h, 0.0f));
                }
                q4s[Q4_H1 + p * H1Q + j] = v;
            }
            __syncthreads();

            // ---- layer 2: C^T[ch][p] = W2^T x H1^T (M=128ch, N=32pts/group, K=64) ----
            #pragma unroll
            for (int ng = 0; ng < 2; ng++) {
                const int n0b = 64 * l2half + 32 * ng;
                if (n0b < tp) {
                    float acc[4][4];
                    #pragma unroll
                    for (int nt = 0; nt < 4; nt++) {
                        acc[nt][0] = 0.f; acc[nt][1] = 0.f; acc[nt][2] = 0.f; acc[nt][3] = 0.f;
                    }
                    #pragma unroll
                    for (int sQ = 0; sQ < 4; sQ++) {
                        const uint4 aQ0 = q4s[Q4_W2 + (16 * wm + g)     * W2Q + 4 * sQ + tq];
                        const uint4 aQ1 = q4s[Q4_W2 + (16 * wm + g + 8) * W2Q + 4 * sQ + tq];
                        #pragma unroll
                        for (int nt = 0; nt < 4; nt++) {
                            const uint4 bQ = q4s[Q4_H1 + (n0b + 8 * nt + g) * H1Q + 4 * sQ + tq];
                            mma8(acc[nt][0], acc[nt][1], acc[nt][2], acc[nt][3],
                                 aQ0.x, aQ1.x, aQ0.y, aQ1.y, bQ.x, bQ.y);
                            mma8(acc[nt][0], acc[nt][1], acc[nt][2], acc[nt][3],
                                 aQ0.z, aQ1.z, aQ0.w, aQ1.w, bQ.z, bQ.w);
                        }
                    }
                    // epilogue: +b2, relu, tf32, scalar stores into H2 quad layout
                    #pragma unroll
                    for (int nt = 0; nt < 4; nt++) {
                        const int p0 = n0b + 8 * nt + 2 * tq;
                        const int b0 = h2sbase + p0 * 144;
                        us[b0]           = f2tf(fmaxf(acc[nt][0] + bb2a, 0.0f));
                        us[b0 + 144]     = f2tf(fmaxf(acc[nt][1] + bb2a, 0.0f));
                        us[b0 + 2]       = f2tf(fmaxf(acc[nt][2] + bb2b, 0.0f));
                        us[b0 + 2 + 144] = f2tf(fmaxf(acc[nt][3] + bb2b, 0.0f));
                    }
                }
            }
            __syncthreads();

            // ---- layer 3: C^T[ch][p] = W3^T x H2^T (M=256ch, N=32pts/group, K=128) + max ----
            #pragma unroll
            for (int ng = 0; ng < 4; ng++) {
                const int n0 = 32 * ng;
                if (n0 >= tp) break;
                float acc[4][4];
                #pragma unroll
                for (int nt = 0; nt < 4; nt++) {
                    acc[nt][0] = 0.f; acc[nt][1] = 0.f; acc[nt][2] = 0.f; acc[nt][3] = 0.f;
                }
                #pragma unroll
                for (int sQ = 0; sQ < 8; sQ++) {
                    #pragma unroll
                    for (int nt = 0; nt < 4; nt++) {
                        const uint4 bQ = q4s[Q4_H2 + (n0 + 8 * nt + g) * H2Q + 4 * sQ + tq];
                        mma8(acc[nt][0], acc[nt][1], acc[nt][2], acc[nt][3],
                             a3r[8 * sQ + 0], a3r[8 * sQ + 1], a3r[8 * sQ + 2], a3r[8 * sQ + 3],
                             bQ.x, bQ.y);
                        mma8(acc[nt][0], acc[nt][1], acc[nt][2], acc[nt][3],
                             a3r[8 * sQ + 4], a3r[8 * sQ + 5], a3r[8 * sQ + 6], a3r[8 * sQ + 7],
                             bQ.z, bQ.w);
                    }
                }
                // masked max-pool over point columns
                #pragma unroll
                for (int nt = 0; nt < 4; nt++) {
                    const int p0 = n0 + 8 * nt + 2 * tq;
                    if (p0 < tp) {
                        chmax0 = fmaxf(chmax0, acc[nt][0]);
                        chmax1 = fmaxf(chmax1, acc[nt][2]);
                    }
                    if (p0 + 1 < tp) {
                        chmax0 = fmaxf(chmax0, acc[nt][1]);
                        chmax1 = fmaxf(chmax1, acc[nt][3]);
                    }
                }
            }
        }

        // ---- reduce max over the 4 tq lanes (covers all point columns) ----
        chmax0 = fmaxf(chmax0, __shfl_xor_sync(0xffffffffu, chmax0, 1));
        chmax0 = fmaxf(chmax0, __shfl_xor_sync(0xffffffffu, chmax0, 2));
        chmax1 = fmaxf(chmax1, __shfl_xor_sync(0xffffffffu, chmax1, 1));
        chmax1 = fmaxf(chmax1, __shfl_xor_sync(0xffffffffu, chmax1, 2));
        if (tq == 0) {
            s[OFF_FEATS + chw + g]     = chmax0 + bb3a;
            s[OFF_FEATS + chw + g + 8] = chmax1 + bb3b;
        }
        __syncthreads();

        // ---- heads: 7 dot products of length 256 (warps 0..6) ----
        if (w < 7) {
            float acc = 0.0f;
            #pragma unroll
            for (int i = 0; i < 8; i++) {
                const int idx = i * 32 + lane;
                acc = fmaf(s[OFF_FEATS + idx], s[OFF_WH + w * 256 + idx], acc);
            }
            #pragma unroll
            for (int o = 16; o > 0; o >>= 1)
                acc += __shfl_xor_sync(0xffffffffu, acc, o);
            if (lane == 0) {
                if (w == 0) out[pid] = acc + s[OFF_BH];
                else        out[NP + pid * 6 + (w - 1)] = acc + s[OFF_BH + w];
            }
        }
    }
}

extern "C" void kernel_launch(void* const* d_in, const int* in_sizes, int n_in,
                              void* d_out, int out_size)
{
    const float* points    = (const float*)d_in[0];
    const int*   counts    = (const int*)  d_in[1];
    const float* proposals = (const float*)d_in[2];
    const float* W1 = (const float*)d_in[3];
    const float* b1 = (const float*)d_in[4];
    const float* W2 = (const float*)d_in[5];
    const float* b2 = (const float*)d_in[6];
    const float* W3 = (const float*)d_in[7];
    const float* b3 = (const float*)d_in[8];
    const float* Wc = (const float*)d_in[9];
    const float* bc = (const float*)d_in[10];
    const float* Wr = (const float*)d_in[11];
    const float* br = (const float*)d_in[12];
    float* out = (float*)d_out;

    int dev = 0, sms = 148;
    cudaGetDevice(&dev);
    cudaDeviceGetAttribute(&sms, cudaDevAttrMultiProcessorCount, dev);
    cudaFuncSetAttribute(refine_kernel,
                         cudaFuncAttributeMaxDynamicSharedMemorySize,
                         SMEM_FLOATS * (int)sizeof(float));

    refine_kernel<<<sms, 512, SMEM_FLOATS * (int)sizeof(float)>>>(
        points, counts, proposals, W1, b1, W2, b2, W3, b3, Wc, bc, Wr, br, out);
}

// round 7
// speedup vs baseline: 5.6219x; 1.1998x over previous
#include <cuda_runtime.h>
#include <math.h>
#include <float.h>

#define NP    2048
#define MAXNP 256

// ---- shared memory layout ----
// uint4 quad arrays first (stride ≡ 4 mod 8 in 16B units -> conflict-free LDS.128),
// then float region. Offsets in the respective units.
#define Q4_H1   0            // [128 pts][20 u4]  (16 used: quad (16s+tq)+{0,4,8,12}, K=64)
#define Q4_H2   2560         // [128 pts][36 u4]  (32 used: K=128)
#define Q4_W2   7168         // [128 ch ][20 u4]  (W2^T quads, K=64)
#define H1Q 20
#define H2Q 36
#define W2Q 20
// float offsets (floats region starts after 9728 u4 = 38912 floats)
#define OFF_WH    38912      // 7*256 head weight columns (cls + 6 reg)
#define OFF_BH    40704      // 8
#define OFF_FEATS 40712      // 256
#define SMEM_FLOATS 40968    // 163,872 bytes

extern __shared__ float s[];

__device__ unsigned g_ticket;

__global__ void reset_ticket_kernel() { g_ticket = 0u; }

__device__ __forceinline__ unsigned f2tf(float f) {
    unsigned u; asm("cvt.rna.tf32.f32 %0, %1;" : "=r"(u) : "f"(f)); return u;
}

__device__ __forceinline__ void mma8(float& c0, float& c1, float& c2, float& c3,
                                     unsigned a0, unsigned a1, unsigned a2, unsigned a3,
                                     unsigned b0, unsigned b1) {
    asm("mma.sync.aligned.m16n8k8.row.col.f32.tf32.tf32.f32 "
        "{%0,%1,%2,%3}, {%4,%5,%6,%7}, {%8,%9}, {%0,%1,%2,%3};"
        : "+f"(c0), "+f"(c1), "+f"(c2), "+f"(c3)
        : "r"(a0), "r"(a1), "r"(a2), "r"(a3), "r"(b0), "r"(b1));
}

__global__ __launch_bounds__(512, 1)
void refine_kernel(const float* __restrict__ points,
                   const int*   __restrict__ counts,
                   const float* __restrict__ proposals,
                   const float* __restrict__ W1, const float* __restrict__ b1,
                   const float* __restrict__ W2, const float* __restrict__ b2,
                   const float* __restrict__ W3, const float* __restrict__ b3,
                   const float* __restrict__ Wc, const float* __restrict__ bc,
                   const float* __restrict__ Wr, const float* __restrict__ br,
                   float* __restrict__ out)
{
    uint4*    q4s = (uint4*)s;
    unsigned* us  = (unsigned*)s;
    __shared__ unsigned s_pid;

    const int tid  = threadIdx.x;
    const int w    = tid >> 5;           // warp 0..15
    const int lane = tid & 31;
    const int g    = lane >> 2;          // groupID 0..7
    const int tq   = lane & 3;           // tid-in-group 0..3

    // ---- stage W2^T quads into smem (tf32): quad(row, s, tq) = k in (16s+tq)+{0,4,8,12} ----
    for (int i = tid; i < 128 * 16; i += 512) {
        const int row = i >> 4, j = i & 15;
        const int sQ = j >> 2, tqQ = j & 3;
        const int k = 16 * sQ + tqQ;
        uint4 v;
        v.x = f2tf(W2[k * 128 + row]);
        v.y = f2tf(W2[(k + 4) * 128 + row]);
        v.z = f2tf(W2[(k + 8) * 128 + row]);
        v.w = f2tf(W2[(k + 12) * 128 + row]);
        q4s[Q4_W2 + row * W2Q + j] = v;
    }
    // ---- head weights/biases ----
    if (tid < 256) {
        s[OFF_WH + tid] = Wc[tid];
        #pragma unroll
        for (int j = 0; j < 6; j++) s[OFF_WH + (1 + j) * 256 + tid] = Wr[tid * 6 + j];
    }
    if (tid == 0) s[OFF_BH] = bc[0];
    if (tid >= 1 && tid < 7) s[OFF_BH + tid] = br[tid - 1];

    // ---- W3 A-fragments: resident in registers for the whole kernel ----
    // warp w owns output channels [16w, 16w+16)
    const int chw = 16 * w;
    unsigned a3r[64];
    #pragma unroll
    for (int ks = 0; ks < 16; ks++) {
        const int k0 = 8 * ks;
        a3r[4 * ks + 0] = f2tf(W3[(k0 + tq)     * 256 + chw + g]);
        a3r[4 * ks + 1] = f2tf(W3[(k0 + tq)     * 256 + chw + g + 8]);
        a3r[4 * ks + 2] = f2tf(W3[(k0 + tq + 4) * 256 + chw + g]);
        a3r[4 * ks + 3] = f2tf(W3[(k0 + tq + 4) * 256 + chw + g + 8]);
    }

    // layer-2 role: warp w handles channels [16*(w&7), +16), point half (w>>3)
    const int wm  = w & 7;
    const int chL2 = 16 * wm + g;
    const float bb2a = b2[chL2];
    const float bb2b = b2[chL2 + 8];
    const float bb3a = b3[chw + g];
    const float bb3b = b3[chw + g + 8];
    const int l2half = w >> 3;
    // H2 quad-layout scalar store index parts: uint idx = H2base + p*144 + wm*16 + (g&3)*4 + (g>>2)
    const int h2sbase = 4 * Q4_H2 + wm * 16 + (g & 3) * 4 + (g >> 2);

    for (;;) {
        if (tid == 0) s_pid = atomicAdd(&g_ticket, 1u);
        __syncthreads();      // publishes s_pid; also orders prev proposal's smem reads
        const unsigned pid = s_pid;
        if (pid >= NP) break;

        const int n = counts[pid];
        if (n < 4) {
            if (tid == 0) out[pid] = s[OFF_BH];
            if (tid < 6)  out[NP + pid * 6 + tid] = s[OFF_BH + 1 + tid];
            continue;
        }

        // proposals row: pid*6 floats = 24*pid bytes -> always 8B aligned.
        const float2 pr0 = __ldg((const float2*)(proposals + pid * 6));      // cen0, cen1
        const float2 pr1 = __ldg((const float2*)(proposals + pid * 6 + 2));  // cen2, size0
        const float2 pr2 = __ldg((const float2*)(proposals + pid * 6 + 4));  // size1, size2
        const float cen0 = pr0.x, cen1 = pr0.y, cen2 = pr1.x;
        const float is0 = 1.0f / (fabsf(pr1.y) + 1e-6f);
        const float is1 = 1.0f / (fabsf(pr2.x) + 1e-6f);
        const float is2 = 1.0f / (fabsf(pr2.y) + 1e-6f);

        float chmax0 = -FLT_MAX, chmax1 = -FLT_MAX;

        for (int p0b = 0; p0b < n; p0b += 128) {
            const int tp = min(128, n - p0b);
            const int tp8 = (tp + 7) & ~7;      // 8-point work granularity

            // ---- layer 1 (scalar): H1 quads, only needed points ----
            for (int i = tid; i < tp8 * 16; i += 512) {
                const int p = i >> 4, j = i & 15;
                const int sQ = j >> 2, tqQ = j & 3;
                const int c = 16 * sQ + tqQ;
                const float* pt = points + (size_t)pid * (MAXNP * 3) + (p0b + p) * 3;
                const float x0 = (pt[0] - cen0) * is0;
                const float x1 = (pt[1] - cen1) * is1;
                const float x2 = (pt[2] - cen2) * is2;
                uint4 v;
                {
                    float h = fmaf(x2, W1[128 + c], fmaf(x1, W1[64 + c], fmaf(x0, W1[c], b1[c])));
                    v.x = f2tf(fmaxf(h, 0.0f));
                }
                {
                    float h = fmaf(x2, W1[128 + c + 4], fmaf(x1, W1[64 + c + 4], fmaf(x0, W1[c + 4], b1[c + 4])));
                    v.y = f2tf(fmaxf(h, 0.0f));
                }
                {
                    float h = fmaf(x2, W1[128 + c + 8], fmaf(x1, W1[64 + c + 8], fmaf(x0, W1[c + 8], b1[c + 8])));
                    v.z = f2tf(fmaxf(h, 0.0f));
                }
                {
                    float h = fmaf(x2, W1[128 + c + 12], fmaf(x1, W1[64 + c + 12], fmaf(x0, W1[c + 12], b1[c + 12])));
                    v.w = f2tf(fmaxf(h, 0.0f));
                }
                q4s[Q4_H1 + p * H1Q + j] = v;
            }
            __syncthreads();

            // ---- layer 2: C^T[ch][p] = W2^T x H1^T (M=128ch, 8-pt groups, K=64) ----
            #pragma unroll
            for (int ng = 0; ng < 2; ng++) {
                const int n0b = 64 * l2half + 32 * ng;
                if (n0b < tp) {
                    const int ntmax = min(4, (tp - n0b + 7) >> 3);
                    float acc[4][4];
                    #pragma unroll
                    for (int nt = 0; nt < 4; nt++) {
                        acc[nt][0] = 0.f; acc[nt][1] = 0.f; acc[nt][2] = 0.f; acc[nt][3] = 0.f;
                    }
                    #pragma unroll
                    for (int sQ = 0; sQ < 4; sQ++) {
                        const uint4 aQ0 = q4s[Q4_W2 + (16 * wm + g)     * W2Q + 4 * sQ + tq];
                        const uint4 aQ1 = q4s[Q4_W2 + (16 * wm + g + 8) * W2Q + 4 * sQ + tq];
                        #pragma unroll
                        for (int nt = 0; nt < 4; nt++) {
                            if (nt < ntmax) {
                                const uint4 bQ = q4s[Q4_H1 + (n0b + 8 * nt + g) * H1Q + 4 * sQ + tq];
                                mma8(acc[nt][0], acc[nt][1], acc[nt][2], acc[nt][3],
                                     aQ0.x, aQ1.x, aQ0.y, aQ1.y, bQ.x, bQ.y);
                                mma8(acc[nt][0], acc[nt][1], acc[nt][2], acc[nt][3],
                                     aQ0.z, aQ1.z, aQ0.w, aQ1.w, bQ.z, bQ.w);
                            }
                        }
                    }
                    // epilogue: +b2, relu, tf32, scalar stores into H2 quad layout
                    #pragma unroll
                    for (int nt = 0; nt < 4; nt++) {
                        if (nt < ntmax) {
                            const int p0 = n0b + 8 * nt + 2 * tq;
                            const int b0 = h2sbase + p0 * 144;
                            us[b0]           = f2tf(fmaxf(acc[nt][0] + bb2a, 0.0f));
                            us[b0 + 144]     = f2tf(fmaxf(acc[nt][1] + bb2a, 0.0f));
                            us[b0 + 2]       = f2tf(fmaxf(acc[nt][2] + bb2b, 0.0f));
                            us[b0 + 2 + 144] = f2tf(fmaxf(acc[nt][3] + bb2b, 0.0f));
                        }
                    }
                }
            }
            __syncthreads();

            // ---- layer 3: C^T[ch][p] = W3^T x H2^T (M=256ch, 8-pt groups, K=128) + max ----
            #pragma unroll
            for (int ng = 0; ng < 4; ng++) {
                const int n0 = 32 * ng;
                if (n0 >= tp) break;
                const int ntmax = min(4, (tp - n0 + 7) >> 3);
                float acc[4][4];
                #pragma unroll
                for (int nt = 0; nt < 4; nt++) {
                    acc[nt][0] = 0.f; acc[nt][1] = 0.f; acc[nt][2] = 0.f; acc[nt][3] = 0.f;
                }
                #pragma unroll
                for (int sQ = 0; sQ < 8; sQ++) {
                    #pragma unroll
                    for (int nt = 0; nt < 4; nt++) {
                        if (nt < ntmax) {
                            const uint4 bQ = q4s[Q4_H2 + (n0 + 8 * nt + g) * H2Q + 4 * sQ + tq];
                            mma8(acc[nt][0], acc[nt][1], acc[nt][2], acc[nt][3],
                                 a3r[8 * sQ + 0], a3r[8 * sQ + 1], a3r[8 * sQ + 2], a3r[8 * sQ + 3],
                                 bQ.x, bQ.y);
                            mma8(acc[nt][0], acc[nt][1], acc[nt][2], acc[nt][3],
                                 a3r[8 * sQ + 4], a3r[8 * sQ + 5], a3r[8 * sQ + 6], a3r[8 * sQ + 7],
                                 bQ.z, bQ.w);
                        }
                    }
                }
                // masked max-pool over point columns
                #pragma unroll
                for (int nt = 0; nt < 4; nt++) {
                    const int p0 = n0 + 8 * nt + 2 * tq;
                    if (p0 < tp) {
                        chmax0 = fmaxf(chmax0, acc[nt][0]);
                        chmax1 = fmaxf(chmax1, acc[nt][2]);
                    }
                    if (p0 + 1 < tp) {
                        chmax0 = fmaxf(chmax0, acc[nt][1]);
                        chmax1 = fmaxf(chmax1, acc[nt][3]);
                    }
                }
            }
        }

        // ---- reduce max over the 4 tq lanes (covers all point columns) ----
        chmax0 = fmaxf(chmax0, __shfl_xor_sync(0xffffffffu, chmax0, 1));
        chmax0 = fmaxf(chmax0, __shfl_xor_sync(0xffffffffu, chmax0, 2));
        chmax1 = fmaxf(chmax1, __shfl_xor_sync(0xffffffffu, chmax1, 1));
        chmax1 = fmaxf(chmax1, __shfl_xor_sync(0xffffffffu, chmax1, 2));
        if (tq == 0) {
            s[OFF_FEATS + chw + g]     = chmax0 + bb3a;
            s[OFF_FEATS + chw + g + 8] = chmax1 + bb3b;
        }
        __syncthreads();

        // ---- heads: 7 dot products of length 256 (warps 0..6) ----
        if (w < 7) {
            float acc = 0.0f;
            #pragma unroll
            for (int i = 0; i < 8; i++) {
                const int idx = i * 32 + lane;
                acc = fmaf(s[OFF_FEATS + idx], s[OFF_WH + w * 256 + idx], acc);
            }
            #pragma unroll
            for (int o = 16; o > 0; o >>= 1)
                acc += __shfl_xor_sync(0xffffffffu, acc, o);
            if (lane == 0) {
                if (w == 0) out[pid] = acc + s[OFF_BH];
                else        out[NP + pid * 6 + (w - 1)] = acc + s[OFF_BH + w];
            }
        }
    }
}

extern "C" void kernel_launch(void* const* d_in, const int* in_sizes, int n_in,
                              void* d_out, int out_size)
{
    const float* points    = (const float*)d_in[0];
    const int*   counts    = (const int*)  d_in[1];
    const float* proposals = (const float*)d_in[2];
    const float* W1 = (const float*)d_in[3];
    const float* b1 = (const float*)d_in[4];
    const float* W2 = (const float*)d_in[5];
    const float* b2 = (const float*)d_in[6];
    const float* W3 = (const float*)d_in[7];
    const float* b3 = (const float*)d_in[8];
    const float* Wc = (const float*)d_in[9];
    const float* bc = (const float*)d_in[10];
    const float* Wr = (const float*)d_in[11];
    const float* br = (const float*)d_in[12];
    float* out = (float*)d_out;

    int dev = 0, sms = 148;
    cudaGetDevice(&dev);
    cudaDeviceGetAttribute(&sms, cudaDevAttrMultiProcessorCount, dev);
    cudaFuncSetAttribute(refine_kernel,
                         cudaFuncAttributeMaxDynamicSharedMemorySize,
                         SMEM_FLOATS * (int)sizeof(float));

    reset_ticket_kernel<<<1, 1>>>();
    refine_kernel<<<sms, 512, SMEM_FLOATS * (int)sizeof(float)>>>(
        points, counts, proposals, W1, b1, W2, b2, W3, b3, Wc, bc, Wr, br, out);
}

// round 8
// speedup vs baseline: 5.7762x; 1.0274x over previous
#include <cuda_runtime.h>
#include <math.h>
#include <float.h>

#define NP    2048
#define MAXNP 256

// ---- shared memory layout ----
// uint4 quad arrays first (stride ≡ 4 mod 8 in 16B units -> conflict-free LDS.128),
// then float region. Offsets in the respective units.
#define Q4_H1   0            // [128 pts][20 u4]  (16 used: quad (16s+tq)+{0,4,8,12}, K=64)
#define Q4_H2   2560         // [128 pts][36 u4]  (32 used: K=128)
#define Q4_W2   7168         // [128 ch ][20 u4]  (W2^T quads, K=64)
#define H1Q 20
#define H2Q 36
#define W2Q 20
// float offsets (floats region starts after 9728 u4 = 38912 floats)
#define OFF_WH    38912      // 7*256 head weight columns (cls + 6 reg)
#define OFF_BH    40704      // 8
#define OFF_FEATS 40712      // 256
#define OFF_PTS   40968      // 768 raw point floats (16B-aligned: 40968*4 % 16 == 0)
#define SMEM_FLOATS 41736    // 166,944 bytes

extern __shared__ float s[];

__device__ unsigned g_ticket;

__global__ void reset_ticket_kernel() { g_ticket = 0u; }

__device__ __forceinline__ unsigned f2tf(float f) {
    unsigned u; asm("cvt.rna.tf32.f32 %0, %1;" : "=r"(u) : "f"(f)); return u;
}

__device__ __forceinline__ void mma8(float& c0, float& c1, float& c2, float& c3,
                                     unsigned a0, unsigned a1, unsigned a2, unsigned a3,
                                     unsigned b0, unsigned b1) {
    asm("mma.sync.aligned.m16n8k8.row.col.f32.tf32.tf32.f32 "
        "{%0,%1,%2,%3}, {%4,%5,%6,%7}, {%8,%9}, {%0,%1,%2,%3};"
        : "+f"(c0), "+f"(c1), "+f"(c2), "+f"(c3)
        : "r"(a0), "r"(a1), "r"(a2), "r"(a3), "r"(b0), "r"(b1));
}

__global__ __launch_bounds__(512, 1)
void refine_kernel(const float* __restrict__ points,
                   const int*   __restrict__ counts,
                   const float* __restrict__ proposals,
                   const float* __restrict__ W1, const float* __restrict__ b1,
                   const float* __restrict__ W2, const float* __restrict__ b2,
                   const float* __restrict__ W3, const float* __restrict__ b3,
                   const float* __restrict__ Wc, const float* __restrict__ bc,
                   const float* __restrict__ Wr, const float* __restrict__ br,
                   float* __restrict__ out)
{
    uint4*    q4s = (uint4*)s;
    unsigned* us  = (unsigned*)s;
    __shared__ unsigned s_pid;

    const int tid  = threadIdx.x;
    const int w    = tid >> 5;           // warp 0..15
    const int lane = tid & 31;
    const int g    = lane >> 2;          // groupID 0..7
    const int tq   = lane & 3;           // tid-in-group 0..3

    // ---- stage W2^T quads into smem (tf32): quad(row, s, tq) = k in (16s+tq)+{0,4,8,12} ----
    for (int i = tid; i < 128 * 16; i += 512) {
        const int row = i >> 4, j = i & 15;
        const int sQ = j >> 2, tqQ = j & 3;
        const int k = 16 * sQ + tqQ;
        uint4 v;
        v.x = f2tf(W2[k * 128 + row]);
        v.y = f2tf(W2[(k + 4) * 128 + row]);
        v.z = f2tf(W2[(k + 8) * 128 + row]);
        v.w = f2tf(W2[(k + 12) * 128 + row]);
        q4s[Q4_W2 + row * W2Q + j] = v;
    }
    // ---- head weights/biases ----
    if (tid < 256) {
        s[OFF_WH + tid] = Wc[tid];
        #pragma unroll
        for (int j = 0; j < 6; j++) s[OFF_WH + (1 + j) * 256 + tid] = Wr[tid * 6 + j];
    }
    if (tid == 0) s[OFF_BH] = bc[0];
    if (tid >= 1 && tid < 7) s[OFF_BH + tid] = br[tid - 1];

    // ---- W3 A-fragments: resident in registers for the whole kernel ----
    // warp w owns output channels [16w, 16w+16)
    const int chw = 16 * w;
    unsigned a3r[64];
    #pragma unroll
    for (int ks = 0; ks < 16; ks++) {
        const int k0 = 8 * ks;
        a3r[4 * ks + 0] = f2tf(W3[(k0 + tq)     * 256 + chw + g]);
        a3r[4 * ks + 1] = f2tf(W3[(k0 + tq)     * 256 + chw + g + 8]);
        a3r[4 * ks + 2] = f2tf(W3[(k0 + tq + 4) * 256 + chw + g]);
        a3r[4 * ks + 3] = f2tf(W3[(k0 + tq + 4) * 256 + chw + g + 8]);
    }

    // layer-2 role: warp w handles channels [16*(w&7), +16), point half (w>>3)
    const int wm  = w & 7;
    const int chL2 = 16 * wm + g;
    const float bb2a = b2[chL2];
    const float bb2b = b2[chL2 + 8];
    const float bb3a = b3[chw + g];
    const float bb3b = b3[chw + g + 8];
    const int l2half = w >> 3;
    // H2 quad-layout scalar store index parts: uint idx = H2base + p*144 + wm*16 + (g&3)*4 + (g>>2)
    const int h2sbase = 4 * Q4_H2 + wm * 16 + (g & 3) * 4 + (g >> 2);

    for (;;) {
        if (tid == 0) s_pid = atomicAdd(&g_ticket, 1u);
        __syncthreads();      // publishes s_pid; also orders prev proposal's smem reads
        const unsigned pid = s_pid;
        if (pid >= NP) break;

        const int n = counts[pid];
        if (n < 4) {
            if (tid == 0) out[pid] = s[OFF_BH];
            if (tid < 6)  out[NP + pid * 6 + tid] = s[OFF_BH + 1 + tid];
            continue;
        }

        // ---- stage this proposal's raw points into smem: one coalesced L2 round-trip ----
        {
            const uint4* gp4 = (const uint4*)(points + (size_t)pid * (MAXNP * 3));
            uint4* sp4 = (uint4*)(s + OFF_PTS);
            const int nf4 = (3 * n + 3) >> 2;     // ceil(3n/4) uint4s, <= 192
            for (int i = tid; i < nf4; i += 512) sp4[i] = __ldg(gp4 + i);
        }

        // proposals row: pid*6 floats = 24*pid bytes -> always 8B aligned.
        const float2 pr0 = __ldg((const float2*)(proposals + pid * 6));      // cen0, cen1
        const float2 pr1 = __ldg((const float2*)(proposals + pid * 6 + 2));  // cen2, size0
        const float2 pr2 = __ldg((const float2*)(proposals + pid * 6 + 4));  // size1, size2
        const float cen0 = pr0.x, cen1 = pr0.y, cen2 = pr1.x;
        const float is0 = 1.0f / (fabsf(pr1.y) + 1e-6f);
        const float is1 = 1.0f / (fabsf(pr2.x) + 1e-6f);
        const float is2 = 1.0f / (fabsf(pr2.y) + 1e-6f);

        __syncthreads();      // points staged before layer-1 reads them

        float chmax0 = -FLT_MAX, chmax1 = -FLT_MAX;

        for (int p0b = 0; p0b < n; p0b += 128) {
            const int tp = min(128, n - p0b);
            const int tp8 = (tp + 7) & ~7;      // 8-point work granularity

            // ---- layer 1 (scalar): H1 quads from smem points ----
            for (int i = tid; i < tp8 * 16; i += 512) {
                const int p = i >> 4, j = i & 15;
                const int sQ = j >> 2, tqQ = j & 3;
                const int c = 16 * sQ + tqQ;
                const float* pt = s + OFF_PTS + (p0b + p) * 3;
                const float x0 = (pt[0] - cen0) * is0;
                const float x1 = (pt[1] - cen1) * is1;
                const float x2 = (pt[2] - cen2) * is2;
                uint4 v;
                {
                    float h = fmaf(x2, W1[128 + c], fmaf(x1, W1[64 + c], fmaf(x0, W1[c], b1[c])));
                    v.x = f2tf(fmaxf(h, 0.0f));
                }
                {
                    float h = fmaf(x2, W1[128 + c + 4], fmaf(x1, W1[64 + c + 4], fmaf(x0, W1[c + 4], b1[c + 4])));
                    v.y = f2tf(fmaxf(h, 0.0f));
                }
                {
                    float h = fmaf(x2, W1[128 + c + 8], fmaf(x1, W1[64 + c + 8], fmaf(x0, W1[c + 8], b1[c + 8])));
                    v.z = f2tf(fmaxf(h, 0.0f));
                }
                {
                    float h = fmaf(x2, W1[128 + c + 12], fmaf(x1, W1[64 + c + 12], fmaf(x0, W1[c + 12], b1[c + 12])));
                    v.w = f2tf(fmaxf(h, 0.0f));
                }
                q4s[Q4_H1 + p * H1Q + j] = v;
            }
            __syncthreads();

            // ---- layer 2: C^T[ch][p] = W2^T x H1^T (M=128ch, 8-pt groups, K=64) ----
            #pragma unroll
            for (int ng = 0; ng < 2; ng++) {
                const int n0b = 64 * l2half + 32 * ng;
                if (n0b < tp) {
                    const int ntmax = min(4, (tp - n0b + 7) >> 3);
                    float acc[4][4];
                    #pragma unroll
                    for (int nt = 0; nt < 4; nt++) {
                        acc[nt][0] = 0.f; acc[nt][1] = 0.f; acc[nt][2] = 0.f; acc[nt][3] = 0.f;
                    }
                    #pragma unroll
                    for (int sQ = 0; sQ < 4; sQ++) {
                        const uint4 aQ0 = q4s[Q4_W2 + (16 * wm + g)     * W2Q + 4 * sQ + tq];
                        const uint4 aQ1 = q4s[Q4_W2 + (16 * wm + g + 8) * W2Q + 4 * sQ + tq];
                        #pragma unroll
                        for (int nt = 0; nt < 4; nt++) {
                            if (nt < ntmax) {
                                const uint4 bQ = q4s[Q4_H1 + (n0b + 8 * nt + g) * H1Q + 4 * sQ + tq];
                                mma8(acc[nt][0], acc[nt][1], acc[nt][2], acc[nt][3],
                                     aQ0.x, aQ1.x, aQ0.y, aQ1.y, bQ.x, bQ.y);
                                mma8(acc[nt][0], acc[nt][1], acc[nt][2], acc[nt][3],
                                     aQ0.z, aQ1.z, aQ0.w, aQ1.w, bQ.z, bQ.w);
                            }
                        }
                    }
                    // epilogue: +b2, relu, tf32, scalar stores into H2 quad layout
                    #pragma unroll
                    for (int nt = 0; nt < 4; nt++) {
                        if (nt < ntmax) {
                            const int p0 = n0b + 8 * nt + 2 * tq;
                            const int b0 = h2sbase + p0 * 144;
                            us[b0]           = f2tf(fmaxf(acc[nt][0] + bb2a, 0.0f));
                            us[b0 + 144]     = f2tf(fmaxf(acc[nt][1] + bb2a, 0.0f));
                            us[b0 + 2]       = f2tf(fmaxf(acc[nt][2] + bb2b, 0.0f));
                            us[b0 + 2 + 144] = f2tf(fmaxf(acc[nt][3] + bb2b, 0.0f));
                        }
                    }
                }
            }
            __syncthreads();

            // ---- layer 3: C^T[ch][p] = W3^T x H2^T (M=256ch, 8-pt groups, K=128) + max ----
            #pragma unroll
            for (int ng = 0; ng < 4; ng++) {
                const int n0 = 32 * ng;
                if (n0 >= tp) break;
                const int ntmax = min(4, (tp - n0 + 7) >> 3);
                float acc[4][4];
                #pragma unroll
                for (int nt = 0; nt < 4; nt++) {
                    acc[nt][0] = 0.f; acc[nt][1] = 0.f; acc[nt][2] = 0.f; acc[nt][3] = 0.f;
                }
                #pragma unroll
                for (int sQ = 0; sQ < 8; sQ++) {
                    #pragma unroll
                    for (int nt = 0; nt < 4; nt++) {
                        if (nt < ntmax) {
                            const uint4 bQ = q4s[Q4_H2 + (n0 + 8 * nt + g) * H2Q + 4 * sQ + tq];
                            mma8(acc[nt][0], acc[nt][1], acc[nt][2], acc[nt][3],
                                 a3r[8 * sQ + 0], a3r[8 * sQ + 1], a3r[8 * sQ + 2], a3r[8 * sQ + 3],
                                 bQ.x, bQ.y);
                            mma8(acc[nt][0], acc[nt][1], acc[nt][2], acc[nt][3],
                                 a3r[8 * sQ + 4], a3r[8 * sQ + 5], a3r[8 * sQ + 6], a3r[8 * sQ + 7],
                                 bQ.z, bQ.w);
                        }
                    }
                }
                // masked max-pool over point columns
                #pragma unroll
                for (int nt = 0; nt < 4; nt++) {
                    const int p0 = n0 + 8 * nt + 2 * tq;
                    if (p0 < tp) {
                        chmax0 = fmaxf(chmax0, acc[nt][0]);
                        chmax1 = fmaxf(chmax1, acc[nt][2]);
                    }
                    if (p0 + 1 < tp) {
                        chmax0 = fmaxf(chmax0, acc[nt][1]);
                        chmax1 = fmaxf(chmax1, acc[nt][3]);
                    }
                }
            }
        }

        // ---- reduce max over the 4 tq lanes (covers all point columns) ----
        chmax0 = fmaxf(chmax0, __shfl_xor_sync(0xffffffffu, chmax0, 1));
        chmax0 = fmaxf(chmax0, __shfl_xor_sync(0xffffffffu, chmax0, 2));
        chmax1 = fmaxf(chmax1, __shfl_xor_sync(0xffffffffu, chmax1, 1));
        chmax1 = fmaxf(chmax1, __shfl_xor_sync(0xffffffffu, chmax1, 2));
        if (tq == 0) {
            s[OFF_FEATS + chw + g]     = chmax0 + bb3a;
            s[OFF_FEATS + chw + g + 8] = chmax1 + bb3b;
        }
        __syncthreads();

        // ---- heads: 7 dot products of length 256 (warps 0..6) ----
        if (w < 7) {
            float acc = 0.0f;
            #pragma unroll
            for (int i = 0; i < 8; i++) {
                const int idx = i * 32 + lane;
                acc = fmaf(s[OFF_FEATS + idx], s[OFF_WH + w * 256 + idx], acc);
            }
            #pragma unroll
            for (int o = 16; o > 0; o >>= 1)
                acc += __shfl_xor_sync(0xffffffffu, acc, o);
            if (lane == 0) {
                if (w == 0) out[pid] = acc + s[OFF_BH];
                else        out[NP + pid * 6 + (w - 1)] = acc + s[OFF_BH + w];
            }
        }
    }
}

extern "C" void kernel_launch(void* const* d_in, const int* in_sizes, int n_in,
                              void* d_out, int out_size)
{
    const float* points    = (const float*)d_in[0];
    const int*   counts    = (const int*)  d_in[1];
    const float* proposals = (const float*)d_in[2];
    const float* W1 = (const float*)d_in[3];
    const float* b1 = (const float*)d_in[4];
    const float* W2 = (const float*)d_in[5];
    const float* b2 = (const float*)d_in[6];
    const float* W3 = (const float*)d_in[7];
    const float* b3 = (const float*)d_in[8];
    const float* Wc = (const float*)d_in[9];
    const float* bc = (const float*)d_in[10];
    const float* Wr = (const float*)d_in[11];
    const float* br = (const float*)d_in[12];
    float* out = (float*)d_out;

    int dev = 0, sms = 148;
    cudaGetDevice(&dev);
    cudaDeviceGetAttribute(&sms, cudaDevAttrMultiProcessorCount, dev);
    cudaFuncSetAttribute(refine_kernel,
                         cudaFuncAttributeMaxDynamicSharedMemorySize,
                         SMEM_FLOATS * (int)sizeof(float));

    reset_ticket_kernel<<<1, 1>>>();
    refine_kernel<<<sms, 512, SMEM_FLOATS * (int)sizeof(float)>>>(
        points, counts, proposals, W1, b1, W2, b2, W3, b3, Wc, bc, Wr, br, out);
}

// round 9
// speedup vs baseline: 5.8254x; 1.0085x over previous
#include <cuda_runtime.h>
#include <math.h>
#include <float.h>

#define NP    2048
#define MAXNP 256

// ---- shared memory layout ----
// uint4 quad arrays first (stride ≡ 4 mod 8 in 16B units -> conflict-free LDS.128),
// then float region. Offsets in the respective units.
#define Q4_H1   0            // [128 pts][20 u4]
#define Q4_H2   2560         // [128 pts][36 u4]
#define Q4_W2   7168         // [128 ch ][20 u4]
#define H1Q 20
#define H2Q 36
#define W2Q 20
#define OFF_WH    38912
#define OFF_BH    40704
#define OFF_FEATS 40712
#define OFF_PTS   40968
#define SMEM_FLOATS 41736    // 166,944 bytes

extern __shared__ float s[];

__device__ unsigned g_ticket;

__global__ void reset_ticket_kernel() { g_ticket = 0u; }

__device__ __forceinline__ unsigned f2tf(float f) {
    unsigned u; asm("cvt.rna.tf32.f32 %0, %1;" : "=r"(u) : "f"(f)); return u;
}

__device__ __forceinline__ void mma8(float& c0, float& c1, float& c2, float& c3,
                                     unsigned a0, unsigned a1, unsigned a2, unsigned a3,
                                     unsigned b0, unsigned b1) {
    asm("mma.sync.aligned.m16n8k8.row.col.f32.tf32.tf32.f32 "
        "{%0,%1,%2,%3}, {%4,%5,%6,%7}, {%8,%9}, {%0,%1,%2,%3};"
        : "+f"(c0), "+f"(c1), "+f"(c2), "+f"(c3)
        : "r"(a0), "r"(a1), "r"(a2), "r"(a3), "r"(b0), "r"(b1));
}

__global__ __launch_bounds__(512, 1)
void refine_kernel(const float* __restrict__ points,
                   const int*   __restrict__ counts,
                   const float* __restrict__ proposals,
                   const float* __restrict__ W1, const float* __restrict__ b1,
                   const float* __restrict__ W2, const float* __restrict__ b2,
                   const float* __restrict__ W3, const float* __restrict__ b3,
                   const float* __restrict__ Wc, const float* __restrict__ bc,
                   const float* __restrict__ Wr, const float* __restrict__ br,
                   float* __restrict__ out)
{
    uint4*    q4s = (uint4*)s;
    unsigned* us  = (unsigned*)s;
    __shared__ unsigned s_pid[2];
    __shared__ float    s_prop[6];
    __shared__ int      s_ncnt;

    const int tid  = threadIdx.x;
    const int w    = tid >> 5;
    const int lane = tid & 31;
    const int g    = lane >> 2;
    const int tq   = lane & 3;

    for (int i = tid; i < 128 * 16; i += 512) {
        const int row = i >> 4, j = i & 15;
        const int sQ = j >> 2, tqQ = j & 3;
        const int k = 16 * sQ + tqQ;
        uint4 v;
        v.x = f2tf(W2[k * 128 + row]);
        v.y = f2tf(W2[(k + 4) * 128 + row]);
        v.z = f2tf(W2[(k + 8) * 128 + row]);
        v.w = f2tf(W2[(k + 12) * 128 + row]);
        q4s[Q4_W2 + row * W2Q + j] = v;
    }
    if (tid < 256) {
        s[OFF_WH + tid] = Wc[tid];
        #pragma unroll
        for (int j = 0; j < 6; j++) s[OFF_WH + (1 + j) * 256 + tid] = Wr[tid * 6 + j];
    }
    if (tid == 0) s[OFF_BH] = bc[0];
    if (tid >= 1 && tid < 7) s[OFF_BH + tid] = br[tid - 1];

    const int chw = 16 * w;
    unsigned a3r[64];
    #pragma unroll
    for (int ks = 0; ks < 16; ks++) {
        const int k0 = 8 * ks;
        a3r[4 * ks + 0] = f2tf(W3[(k0 + tq)     * 256 + chw + g]);
        a3r[4 * ks + 1] = f2tf(W3[(k0 + tq)     * 256 + chw + g + 8]);
        a3r[4 * ks + 2] = f2tf(W3[(k0 + tq + 4) * 256 + chw + g]);
        a3r[4 * ks + 3] = f2tf(W3[(k0 + tq + 4) * 256 + chw + g + 8]);
    }

    const int wm  = w & 7;
    const int chL2 = 16 * wm + g;
    const float bb2a = b2[chL2];
    const float bb2b = b2[chL2 + 8];
    const float bb3a = b3[chw + g];
    const float bb3b = b3[chw + g + 8];
    const int l2half = w >> 3;
    const int h2sbase = 4 * Q4_H2 + wm * 16 + (g & 3) * 4 + (g >> 2);

    if (tid == 0) s_pid[0] = atomicAdd(&g_ticket, 1u);
    __syncthreads();

    {   // prologue staging for first proposal
        const unsigned pid0 = s_pid[0];
        if (pid0 < NP) {
            const int nn = counts[pid0];
            if (tid == 0) s_ncnt = nn;
            if (tid >= 32 && tid < 38) s_prop[tid - 32] = proposals[pid0 * 6 + (tid - 32)];
            const uint4* gp4 = (const uint4*)(points + (size_t)pid0 * (MAXNP * 3));
            uint4* sp4 = (uint4*)(s + OFF_PTS);
            const int nf4 = (3 * nn + 3) >> 2;
            for (int i = tid; i < nf4; i += 512) sp4[i] = __ldg(gp4 + i);
        }
    }
    __syncthreads();

    int par = 0;
    for (;;) {
        const unsigned pid = s_pid[par];
        if (pid >= NP) break;
        if (tid == 0) s_pid[par ^ 1] = atomicAdd(&g_ticket, 1u);
        const int n = s_ncnt;
        const bool valid = (n >= 4);

        float chmax0 = -FLT_MAX, chmax1 = -FLT_MAX;

        if (valid) {
            const float cen0 = s_prop[0], cen1 = s_prop[1], cen2 = s_prop[2];
            const float is0 = 1.0f / (fabsf(s_prop[3]) + 1e-6f);
            const float is1 = 1.0f / (fabsf(s_prop[4]) + 1e-6f);
            const float is2 = 1.0f / (fabsf(s_prop[5]) + 1e-6f);

            auto do_l1 = [&](int base, int cnt8) {   // cnt8 = point count rounded up to 8
                for (int i = tid; i < cnt8 * 16; i += 512) {
                    const int p = i >> 4, j = i & 15;
                    const int sQ = j >> 2, tqQ = j & 3;
                    const int c = 16 * sQ + tqQ;
                    const float* pt = s + OFF_PTS + (base + p) * 3;
                    const float x0 = (pt[0] - cen0) * is0;
                    const float x1 = (pt[1] - cen1) * is1;
                    const float x2 = (pt[2] - cen2) * is2;
                    uint4 v;
                    {
                        float h = fmaf(x2, W1[128 + c], fmaf(x1, W1[64 + c], fmaf(x0, W1[c], b1[c])));
                        v.x = f2tf(fmaxf(h, 0.0f));
                    }
                    {
                        float h = fmaf(x2, W1[128 + c + 4], fmaf(x1, W1[64 + c + 4], fmaf(x0, W1[c + 4], b1[c + 4])));
                        v.y = f2tf(fmaxf(h, 0.0f));
                    }
                    {
                        float h = fmaf(x2, W1[128 + c + 8], fmaf(x1, W1[64 + c + 8], fmaf(x0, W1[c + 8], b1[c + 8])));
                        v.z = f2tf(fmaxf(h, 0.0f));
                    }
                    {
                        float h = fmaf(x2, W1[128 + c + 12], fmaf(x1, W1[64 + c + 12], fmaf(x0, W1[c + 12], b1[c + 12])));
                        v.w = f2tf(fmaxf(h, 0.0f));
                    }
                    q4s[Q4_H1 + p * H1Q + j] = v;
                }
            };

            {
                const int tp0 = min(128, n);
                do_l1(0, (tp0 + 7) & ~7);
            }
            __syncthreads();

            for (int p0b = 0; p0b < n; p0b += 128) {
                const int tp = min(128, n - p0b);

                #pragma unroll
                for (int ng = 0; ng < 2; ng++) {
                    const int n0b = 64 * l2half + 32 * ng;
                    if (n0b < tp) {
                        const int ntmax = min(4, (tp - n0b + 7) >> 3);
                        float acc[4][4];
                        #pragma unroll
                        for (int nt = 0; nt < 4; nt++) {
                            acc[nt][0] = 0.f; acc[nt][1] = 0.f; acc[nt][2] = 0.f; acc[nt][3] = 0.f;
                        }
                        #pragma unroll
                        for (int sQ = 0; sQ < 4; sQ++) {
                            const uint4 aQ0 = q4s[Q4_W2 + (16 * wm + g)     * W2Q + 4 * sQ + tq];
                            const uint4 aQ1 = q4s[Q4_W2 + (16 * wm + g + 8) * W2Q + 4 * sQ + tq];
                            #pragma unroll
                            for (int nt = 0; nt < 4; nt++) {
                                if (nt < ntmax) {
                                    const uint4 bQ = q4s[Q4_H1 + (n0b + 8 * nt + g) * H1Q + 4 * sQ + tq];
                                    mma8(acc[nt][0], acc[nt][1], acc[nt][2], acc[nt][3],
                                         aQ0.x, aQ1.x, aQ0.y, aQ1.y, bQ.x, bQ.y);
                                    mma8(acc[nt][0], acc[nt][1], acc[nt][2], acc[nt][3],
                                         aQ0.z, aQ1.z, aQ0.w, aQ1.w, bQ.z, bQ.w);
                                }
                            }
                        }
                        #pragma unroll
                        for (int nt = 0; nt < 4; nt++) {
                            if (nt < ntmax) {
                                const int p0 = n0b + 8 * nt + 2 * tq;
                                const int b0 = h2sbase + p0 * 144;
                                us[b0]           = f2tf(fmaxf(acc[nt][0] + bb2a, 0.0f));
                                us[b0 + 144]     = f2tf(fmaxf(acc[nt][1] + bb2a, 0.0f));
                                us[b0 + 2]       = f2tf(fmaxf(acc[nt][2] + bb2b, 0.0f));
                                us[b0 + 2 + 144] = f2tf(fmaxf(acc[nt][3] + bb2b, 0.0f));
                            }
                        }
                    }
                }
                __syncthreads();

                #pragma unroll
                for (int ng = 0; ng < 4; ng++) {
                    const int n0 = 32 * ng;
                    if (n0 >= tp) break;
                    const int ntmax = min(4, (tp - n0 + 7) >> 3);
                    float acc[4][4];
                    #pragma unroll
                    for (int nt = 0; nt < 4; nt++) {
                        acc[nt][0] = 0.f; acc[nt][1] = 0.f; acc[nt][2] = 0.f; acc[nt][3] = 0.f;
                    }
                    #pragma unroll
                    for (int sQ = 0; sQ < 8; sQ++) {
                        #pragma unroll
                        for (int nt = 0; nt < 4; nt++) {
                            if (nt < ntmax) {
                                const uint4 bQ = q4s[Q4_H2 + (n0 + 8 * nt + g) * H2Q + 4 * sQ + tq];
                                mma8(acc[nt][0], acc[nt][1], acc[nt][2], acc[nt][3],
                                     a3r[8 * sQ + 0], a3r[8 * sQ + 1], a3r[8 * sQ + 2], a3r[8 * sQ + 3],
                                     bQ.x, bQ.y);
                                mma8(acc[nt][0], acc[nt][1], acc[nt][2], acc[nt][3],
                                     a3r[8 * sQ + 4], a3r[8 * sQ + 5], a3r[8 * sQ + 6], a3r[8 * sQ + 7],
                                     bQ.z, bQ.w);
                            }
                        }
                    }
                    #pragma unroll
                    for (int nt = 0; nt < 4; nt++) {
                        const int p0 = n0 + 8 * nt + 2 * tq;
                        if (p0 < tp) {
                            chmax0 = fmaxf(chmax0, acc[nt][0]);
                            chmax1 = fmaxf(chmax1, acc[nt][2]);
                        }
                        if (p0 + 1 < tp) {
                            chmax0 = fmaxf(chmax0, acc[nt][1]);
                            chmax1 = fmaxf(chmax1, acc[nt][3]);
                        }
                    }
                }
                if (p0b + 128 < n) {
                    const int tpn = min(128, n - p0b - 128);
                    do_l1(p0b + 128, (tpn + 7) & ~7);
                    __syncthreads();
                }
            }

            chmax0 = fmaxf(chmax0, __shfl_xor_sync(0xffffffffu, chmax0, 1));
            chmax0 = fmaxf(chmax0, __shfl_xor_sync(0xffffffffu, chmax0, 2));
            chmax1 = fmaxf(chmax1, __shfl_xor_sync(0xffffffffu, chmax1, 1));
            chmax1 = fmaxf(chmax1, __shfl_xor_sync(0xffffffffu, chmax1, 2));
            if (tq == 0) {
                s[OFF_FEATS + chw + g]     = chmax0 + bb3a;
                s[OFF_FEATS + chw + g + 8] = chmax1 + bb3b;
            }
        }

        __syncthreads();   // T1
        const unsigned npid = s_pid[par ^ 1];

        if (w < 7) {
            if (valid) {
                float acc = 0.0f;
                #pragma unroll
                for (int i = 0; i < 8; i++) {
                    const int idx = i * 32 + lane;
                    acc = fmaf(s[OFF_FEATS + idx], s[OFF_WH + w * 256 + idx], acc);
                }
                #pragma unroll
                for (int o = 16; o > 0; o >>= 1)
                    acc += __shfl_xor_sync(0xffffffffu, acc, o);
                if (lane == 0) {
                    if (w == 0) out[pid] = acc + s[OFF_BH];
                    else        out[NP + pid * 6 + (w - 1)] = acc + s[OFF_BH + w];
                }
            } else if (lane == 0) {
                if (w == 0) out[pid] = s[OFF_BH];
                else        out[NP + pid * 6 + (w - 1)] = s[OFF_BH + w];
            }
        } else if (w == 7) {
            if (npid < NP) {
                if (lane < 6) s_prop[lane] = proposals[npid * 6 + lane];
                if (lane == 6) s_ncnt = counts[npid];
            }
        } else {
            if (npid < NP) {
                const int nn = counts[npid];
                const uint4* gp4 = (const uint4*)(points + (size_t)npid * (MAXNP * 3));
                uint4* sp4 = (uint4*)(s + OFF_PTS);
                const int nf4 = (3 * nn + 3) >> 2;
                for (int i = tid - 256; i < nf4; i += 256) sp4[i] = __ldg(gp4 + i);
            }
        }
        __syncthreads();   // T2
        par ^= 1;
    }
}

extern "C" void kernel_launch(void* const* d_in, const int* in_sizes, int n_in,
                              void* d_out, int out_size)
{
    const float* points    = (const float*)d_in[0];
    const int*   counts    = (const int*)  d_in[1];
    const float* proposals = (const float*)d_in[2];
    const float* W1 = (const float*)d_in[3];
    const float* b1 = (const float*)d_in[4];
    const float* W2 = (const float*)d_in[5];
    const float* b2 = (const float*)d_in[6];
    const float* W3 = (const float*)d_in[7];
    const float* b3 = (const float*)d_in[8];
    const float* Wc = (const float*)d_in[9];
    const float* bc = (const float*)d_in[10];
    const float* Wr = (const float*)d_in[11];
    const float* br = (const float*)d_in[12];
    float* out = (float*)d_out;

    int dev = 0, sms = 148;
    cudaGetDevice(&dev);
    cudaDeviceGetAttribute(&sms, cudaDevAttrMultiProcessorCount, dev);
    cudaFuncSetAttribute(refine_kernel,
                         cudaFuncAttributeMaxDynamicSharedMemorySize,
                         SMEM_FLOATS * (int)sizeof(float));

    reset_ticket_kernel<<<1, 1>>>();
    refine_kernel<<<sms, 512, SMEM_FLOATS * (int)sizeof(float)>>>(
        points, counts, proposals, W1, b1, W2, b2, W3, b3, Wc, bc, Wr, br, out);
}